// round 2
// baseline (speedup 1.0000x reference)
#include <cuda_runtime.h>
#include <math.h>

// Problem constants
#define BB 64
#define SS 512
#define DD 1024
#define HH 1024
#define NG 3072                 // 3*HH (r | z | n gate pre-activations)
#define LW ((DD + HH) * HH)     // per-layer weight element count (2048*1024)
#define NCTA 128                // persistent recurrence grid (<= 148 SMs, co-resident)

// ---------------------------------------------------------------------------
// Scratch (static __device__ globals — no allocation at runtime)
// ---------------------------------------------------------------------------
__device__ float g_Gx[(size_t)SS * BB * NG];    // input-side gate preacts (+bias)
__device__ float g_hseq[(size_t)SS * BB * HH];  // layer-0 output sequence [t*B+b, H]
__device__ float g_h[BB * HH];                  // current hidden state
__device__ float g_rh[BB * HH];                 // r * h
__device__ float g_z[BB * HH];                  // z gate
__device__ float g_part1[32 * 4 * 64 * 64];     // split-K partials, phase 1 (32 ntiles x 4 ks)
__device__ float g_part2[16 * 8 * 64 * 64];     // split-K partials, phase 2 (16 ntiles x 8 ks)
__device__ volatile unsigned g_barrier;         // monotonic grid barrier counter

// ---------------------------------------------------------------------------
__global__ void init_kernel() {
    int i = blockIdx.x * blockDim.x + threadIdx.x;
    if (i < BB * HH) g_h[i] = 0.f;
    if (i == 0) g_barrier = 0u;
}

// ---------------------------------------------------------------------------
// Grid-wide barrier: monotonic counter, all NCTA CTAs co-resident (wave 1).
// ---------------------------------------------------------------------------
__device__ __forceinline__ void grid_barrier(unsigned* target) {
    __syncthreads();
    if (threadIdx.x == 0) {
        __threadfence();
        atomicAdd((unsigned*)&g_barrier, 1u);
        *target += NCTA;
        while (g_barrier < *target) { __nanosleep(64); }
        __threadfence();
    }
    __syncthreads();
}

// ---------------------------------------------------------------------------
// Precompute: Gx[m, gate*H + j] = A[m,:] @ W_gate[0:D, j] + b_gate[j]
// A = x (layer 0, [B,S,D] layout) or g_hseq (layer 1). m = s*B + b.
// Tile: 128(M) x 64(N), BK=8, 256 threads, 8x4 per-thread microtile.
// ---------------------------------------------------------------------------
__global__ void precompute_kernel(const float* __restrict__ x,
                                  const float* __restrict__ Wr,
                                  const float* __restrict__ Wz,
                                  const float* __restrict__ Wh,
                                  const float* __restrict__ br,
                                  const float* __restrict__ bz,
                                  const float* __restrict__ bh,
                                  int layer) {
    __shared__ float As[8][128];
    __shared__ float Bs[8][68];

    const int m0 = blockIdx.y * 128;
    const int n0 = blockIdx.x * 64;           // tiles never straddle a gate
    const int gate = n0 >> 10;                // 0=r, 1=z, 2=n
    const int j0 = n0 & 1023;

    const float* W = (gate == 0 ? Wr : gate == 1 ? Wz : Wh) + (size_t)layer * LW;
    const float* bias = (gate == 0 ? br : gate == 1 ? bz : bh) + layer * HH;

    const int tid = threadIdx.x;
    const int ty = tid >> 4;
    const int tx = tid & 15;

    float acc[8][4];
#pragma unroll
    for (int i = 0; i < 8; i++)
#pragma unroll
        for (int j = 0; j < 4; j++) acc[i][j] = 0.f;

    const int arow = tid >> 1;                // 0..127
    const int akk = (tid & 1) * 4;            // 0 or 4
    const int m = m0 + arow;
    const float* Aptr;
    size_t a_base;
    if (layer == 0) {
        int s = m >> 6, b = m & 63;
        Aptr = x;
        a_base = ((size_t)b * SS + s) * DD;
    } else {
        Aptr = g_hseq;
        a_base = (size_t)m * HH;
    }
    const int bkk = tid >> 4;                 // 0..7 for tid<128
    const int bj = (tid & 15) * 4;

    for (int k0 = 0; k0 < DD; k0 += 8) {
        float4 av = *(const float4*)(Aptr + a_base + k0 + akk);
        As[akk + 0][arow] = av.x;
        As[akk + 1][arow] = av.y;
        As[akk + 2][arow] = av.z;
        As[akk + 3][arow] = av.w;
        if (tid < 128) {
            float4 bv = *(const float4*)(W + (size_t)(k0 + bkk) * HH + j0 + bj);
            Bs[bkk][bj + 0] = bv.x;
            Bs[bkk][bj + 1] = bv.y;
            Bs[bkk][bj + 2] = bv.z;
            Bs[bkk][bj + 3] = bv.w;
        }
        __syncthreads();
#pragma unroll
        for (int kk = 0; kk < 8; kk++) {
            float a[8], b[4];
#pragma unroll
            for (int i = 0; i < 8; i++) a[i] = As[kk][ty * 8 + i];
#pragma unroll
            for (int j = 0; j < 4; j++) b[j] = Bs[kk][tx * 4 + j];
#pragma unroll
            for (int i = 0; i < 8; i++)
#pragma unroll
                for (int j = 0; j < 4; j++) acc[i][j] += a[i] * b[j];
        }
        __syncthreads();
    }

#pragma unroll
    for (int i = 0; i < 8; i++) {
        int mrow = m0 + ty * 8 + i;
        size_t base = (size_t)mrow * NG + n0;
#pragma unroll
        for (int j = 0; j < 4; j++) {
            int c = tx * 4 + j;
            g_Gx[base + c] = acc[i][j] + bias[j0 + c];
        }
    }
}

// ---------------------------------------------------------------------------
// Persistent recurrence kernel: one launch per layer, all 512 steps.
// NCTA=128 CTAs, 256 threads.
//  phase1: c -> ntile=c>>2 (0..31: r|z cols), ks=c&3 (K=256 each)
//  phase2: c -> ntile=c>>3 (0..15), ks=c&7 (K=128 each)
// ---------------------------------------------------------------------------
__global__ void __launch_bounds__(256, 1)
recur_kernel(const float* __restrict__ Wr,
             const float* __restrict__ Wz,
             const float* __restrict__ Wh,
             int layer, float* __restrict__ out) {
    __shared__ float As[8][64];
    __shared__ float Bs[8][68];

    const int c = blockIdx.x;
    const int tid = threadIdx.x;
    const int ty = tid >> 4, tx = tid & 15;

    // phase1 geometry
    const int nt1 = c >> 2;               // 0..31
    const int ks1 = c & 3;                // 0..3
    const int kbase1 = ks1 * 256;
    const float* W1 = ((nt1 < 16) ? Wr : Wz) + (size_t)layer * LW;
    const int j0_1 = (nt1 & 15) * 64;
    // phase2 geometry
    const int nt2 = c >> 3;               // 0..15
    const int ks2 = c & 7;                // 0..7
    const int kbase2 = ks2 * 128;
    const float* W2 = Wh + (size_t)layer * LW;
    const int j0_2 = nt2 * 64;

    const int arow = tid >> 2;            // 0..63
    const int akk = (tid & 3) * 2;        // 0,2,4,6
    const int bkk = tid >> 4;             // 0..7 (tid<128)
    const int bj = (tid & 15) * 4;

    unsigned target = 0;

    for (int t = 0; t < SS; ++t) {
        // ---------------- phase 1 compute: h @ [Wr_h | Wz_h] partial -------
        {
            float acc[4][4];
#pragma unroll
            for (int i = 0; i < 4; i++)
#pragma unroll
                for (int j = 0; j < 4; j++) acc[i][j] = 0.f;

            for (int k0 = 0; k0 < 256; k0 += 8) {
                float2 av = *(const float2*)(g_h + arow * HH + kbase1 + k0 + akk);
                As[akk + 0][arow] = av.x;
                As[akk + 1][arow] = av.y;
                if (tid < 128) {
                    float4 bv = *(const float4*)(W1 + (size_t)(DD + kbase1 + k0 + bkk) * HH + j0_1 + bj);
                    Bs[bkk][bj + 0] = bv.x;
                    Bs[bkk][bj + 1] = bv.y;
                    Bs[bkk][bj + 2] = bv.z;
                    Bs[bkk][bj + 3] = bv.w;
                }
                __syncthreads();
#pragma unroll
                for (int kk = 0; kk < 8; kk++) {
                    float a[4], b[4];
#pragma unroll
                    for (int i = 0; i < 4; i++) a[i] = As[kk][ty * 4 + i];
#pragma unroll
                    for (int j = 0; j < 4; j++) b[j] = Bs[kk][tx * 4 + j];
#pragma unroll
                    for (int i = 0; i < 4; i++)
#pragma unroll
                        for (int j = 0; j < 4; j++) acc[i][j] += a[i] * b[j];
                }
                __syncthreads();
            }
            float* part = g_part1 + (size_t)c * 4096;
#pragma unroll
            for (int i = 0; i < 4; i++)
#pragma unroll
                for (int j = 0; j < 4; j++)
                    part[(ty * 4 + i) * 64 + tx * 4 + j] = acc[i][j];
        }
        grid_barrier(&target);

        // ---------------- epilogue 1: reduce + sigmoid -> rh, z ------------
        {
            const int e0 = c * 1024;      // 64*2048 / 128
            for (int i = tid; i < 1024; i += 256) {
                int e = e0 + i;
                int row = e >> 11;
                int col = e & 2047;
                int nt = col >> 6;
                int cc = col & 63;
                float sum = 0.f;
#pragma unroll
                for (int p = 0; p < 4; p++)
                    sum += g_part1[((size_t)(nt * 4 + p)) * 4096 + row * 64 + cc];
                int m = t * 64 + row;
                float pre = sum + g_Gx[(size_t)m * NG + col];
                float gv = 1.f / (1.f + expf(-pre));
                if (col < 1024)
                    g_rh[row * HH + col] = gv * g_h[row * HH + col];
                else
                    g_z[row * HH + (col - 1024)] = gv;
            }
        }
        grid_barrier(&target);

        // ---------------- phase 2 compute: (r*h) @ Wh_h partial ------------
        {
            float acc[4][4];
#pragma unroll
            for (int i = 0; i < 4; i++)
#pragma unroll
                for (int j = 0; j < 4; j++) acc[i][j] = 0.f;

            for (int k0 = 0; k0 < 128; k0 += 8) {
                float2 av = *(const float2*)(g_rh + arow * HH + kbase2 + k0 + akk);
                As[akk + 0][arow] = av.x;
                As[akk + 1][arow] = av.y;
                if (tid < 128) {
                    float4 bv = *(const float4*)(W2 + (size_t)(DD + kbase2 + k0 + bkk) * HH + j0_2 + bj);
                    Bs[bkk][bj + 0] = bv.x;
                    Bs[bkk][bj + 1] = bv.y;
                    Bs[bkk][bj + 2] = bv.z;
                    Bs[bkk][bj + 3] = bv.w;
                }
                __syncthreads();
#pragma unroll
                for (int kk = 0; kk < 8; kk++) {
                    float a[4], b[4];
#pragma unroll
                    for (int i = 0; i < 4; i++) a[i] = As[kk][ty * 4 + i];
#pragma unroll
                    for (int j = 0; j < 4; j++) b[j] = Bs[kk][tx * 4 + j];
#pragma unroll
                    for (int i = 0; i < 4; i++)
#pragma unroll
                        for (int j = 0; j < 4; j++) acc[i][j] += a[i] * b[j];
                }
                __syncthreads();
            }
            float* part = g_part2 + (size_t)c * 4096;
#pragma unroll
            for (int i = 0; i < 4; i++)
#pragma unroll
                for (int j = 0; j < 4; j++)
                    part[(ty * 4 + i) * 64 + tx * 4 + j] = acc[i][j];
        }
        grid_barrier(&target);

        // ---------------- epilogue 2: reduce + tanh + h update -------------
        {
            const int e0 = c * 512;       // 64*1024 / 128
            for (int i = tid; i < 512; i += 256) {
                int e = e0 + i;
                int row = e >> 10;
                int col = e & 1023;
                int nt = col >> 6;
                int cc = col & 63;
                float sum = 0.f;
#pragma unroll
                for (int p = 0; p < 8; p++)
                    sum += g_part2[((size_t)(nt * 8 + p)) * 4096 + row * 64 + cc];
                int m = t * 64 + row;
                float nv = tanhf(sum + g_Gx[(size_t)m * NG + 2048 + col]);
                float z = g_z[row * HH + col];
                float hold = g_h[row * HH + col];
                float hnew = (1.f - z) * nv + z * hold;
                g_h[row * HH + col] = hnew;
                if (layer == 0)
                    g_hseq[((size_t)t * 64 + row) * HH + col] = hnew;
                else
                    out[((size_t)row * SS + t) * HH + col] = hnew;
            }
        }
        grid_barrier(&target);
    }
}

// ---------------------------------------------------------------------------
extern "C" void kernel_launch(void* const* d_in, const int* in_sizes, int n_in,
                              void* d_out, int out_size) {
    const float* x  = (const float*)d_in[0];
    const float* Wr = (const float*)d_in[1];
    const float* Wz = (const float*)d_in[2];
    const float* Wh = (const float*)d_in[3];
    const float* br = (const float*)d_in[4];
    const float* bz = (const float*)d_in[5];
    const float* bh = (const float*)d_in[6];
    float* out = (float*)d_out;

    for (int layer = 0; layer < 2; ++layer) {
        dim3 pgrid(NG / 64, (SS * BB) / 128);   // (48, 256)
        precompute_kernel<<<pgrid, 256>>>(x, Wr, Wz, Wh, br, bz, bh, layer);
        init_kernel<<<(BB * HH + 255) / 256, 256>>>();
        recur_kernel<<<NCTA, 256>>>(Wr, Wz, Wh, layer, out);
    }
}